// round 7
// baseline (speedup 1.0000x reference)
#include <cuda_runtime.h>

#define B_  16
#define N_  4096
#define D_  1024
#define K_  2048

#define TOK_ 32          // tokens per fused block
#define BLKS_PER_B_ (N_ / TOK_)   // 128

// XOR swizzle for u64 smem (16 double-banks): spreads any 2^k-strided
// pattern across all residues mod 16.
#define SW(i) ((i) ^ (((i) >> 4) & 15))

typedef unsigned long long ull;

__device__ int   g_rank[B_ * N_];
__device__ float g_partial[B_ * BLKS_PER_B_ * D_];

__device__ __forceinline__ unsigned ord32(float v) {
    unsigned bits = __float_as_uint(v);
    return (bits & 0x80000000u) ? ~bits : (bits | 0x80000000u);
}

__device__ __forceinline__ void cswap(ull& x, ull& y, bool desc) {
    // descending: larger first
    const bool sw = desc ? (x < y) : (x > y);
    const ull a = sw ? y : x;
    const ull b = sw ? x : y;
    x = a; y = b;
}

// -------------------------------------------------------------------------
// Kernel A: per-batch bitonic sort -> exact descending rank.
// grid (B), block 1024, 32KB smem of u64 keys (XOR-swizzled layout).
// key = (ord32(v) << 12) | (4095 - idx): descending u64 order reproduces
// jax.lax.top_k exactly (descending by value, ties by smaller index first).
// Register-blocked: each thread owns the 4-element group
// {a, a+j/2, a+j, a+j+j/2} and runs TWO stages per __syncthreads.
// -------------------------------------------------------------------------
__global__ void __launch_bounds__(1024)
sort_rank_kernel(const float* __restrict__ attn) {
    __shared__ ull sk[N_];
    const int b = blockIdx.x;
    const int t = threadIdx.x;

    #pragma unroll
    for (int p = 0; p < N_ / 1024; p++) {
        const int i = p * 1024 + t;
        sk[SW(i)] = ((ull)ord32(attn[b * N_ + i]) << 12) |
                    (unsigned)(4095 - i);
    }
    __syncthreads();

    #pragma unroll 1
    for (int k = 2; k <= N_; k <<= 1) {
        int j = k >> 1;
        #pragma unroll 1
        while (j >= 2) {
            const int j2 = j >> 1;
            const int s  = __popc(j2 - 1);               // log2(j2)
            const int a  = (t & (j2 - 1)) | ((t >> s) << (s + 2));
            ull e0 = sk[SW(a)];
            ull e1 = sk[SW(a + j2)];
            ull e2 = sk[SW(a + j)];
            ull e3 = sk[SW(a + j + j2)];
            const bool desc = ((a & k) == 0);
            // stage j: (e0,e2), (e1,e3)
            cswap(e0, e2, desc);
            cswap(e1, e3, desc);
            // stage j/2: (e0,e1), (e2,e3)
            cswap(e0, e1, desc);
            cswap(e2, e3, desc);
            sk[SW(a)]          = e0;
            sk[SW(a + j2)]     = e1;
            sk[SW(a + j)]      = e2;
            sk[SW(a + j + j2)] = e3;
            __syncthreads();
            j >>= 2;
        }
        if (j == 1) {
            // single stage j=1: 2 contiguous pairs per thread
            const int a = 4 * t;
            ull e0 = sk[SW(a)],     e1 = sk[SW(a + 1)];
            ull e2 = sk[SW(a + 2)], e3 = sk[SW(a + 3)];
            cswap(e0, e1, (a & k) == 0);
            cswap(e2, e3, ((a + 2) & k) == 0);
            sk[SW(a)]     = e0; sk[SW(a + 1)] = e1;
            sk[SW(a + 2)] = e2; sk[SW(a + 3)] = e3;
            __syncthreads();
        }
    }

    #pragma unroll
    for (int p = 0; p < N_ / 1024; p++) {
        const int pos = p * 1024 + t;
        const int idx = 4095 - (int)(sk[SW(pos)] & 0xFFFu);
        g_rank[b * N_ + idx] = pos;
    }
}

// -------------------------------------------------------------------------
// Kernel B: fused gather + pruned-sum. grid (BLKS_PER_B, B), block 256.
// Streams TOK_ consecutive token rows (sequential 128KB read per block).
// Per-token branch is uniform across the block (no divergence):
//   rank < K : write row to out[b, rank, :]
//   else     : accumulate into per-thread float4 partial
// -------------------------------------------------------------------------
__global__ void __launch_bounds__(256)
fused_kernel(const float* __restrict__ seq, float* __restrict__ out) {
    const int b   = blockIdx.y;
    const int blk = blockIdx.x;
    const int t   = threadIdx.x;
    const int n0  = blk * TOK_;

    const float4* __restrict__ src =
        reinterpret_cast<const float4*>(seq + ((size_t)(b * N_ + n0)) * D_);
    const int* __restrict__ rnk = g_rank + b * N_ + n0;

    float4 acc = make_float4(0.f, 0.f, 0.f, 0.f);

    #pragma unroll 8
    for (int k = 0; k < TOK_; k++) {
        const float4 v = src[k * (D_ / 4) + t];
        const int r = rnk[k];
        if (r < K_) {
            reinterpret_cast<float4*>(
                out + ((size_t)(b * (K_ + 1) + r)) * D_)[t] = v;
        } else {
            acc.x += v.x; acc.y += v.y; acc.z += v.z; acc.w += v.w;
        }
    }

    reinterpret_cast<float4*>(g_partial)
        [((size_t)b * BLKS_PER_B_ + blk) * (D_ / 4) + t] = acc;
}

// -------------------------------------------------------------------------
// Kernel C: reduce partials, write mixup row out[b, K, :].
// grid (B, 16), block 256. rem_cnt = 2048 + 1e-10 == 2048.0f in fp32.
// -------------------------------------------------------------------------
__global__ void __launch_bounds__(256)
rem_kernel(float* __restrict__ out) {
    const int b  = blockIdx.x;
    const int g  = threadIdx.x & 15;
    const int s  = threadIdx.x >> 4;
    const int c4 = blockIdx.y * 16 + g;

    const float4* __restrict__ p =
        reinterpret_cast<const float4*>(g_partial) +
        (size_t)b * BLKS_PER_B_ * (D_ / 4) + c4;

    float4 a = make_float4(0.f, 0.f, 0.f, 0.f);
    #pragma unroll
    for (int m = 0; m < 8; m++) {
        const float4 v = p[(size_t)(s + 16 * m) * (D_ / 4)];
        a.x += v.x; a.y += v.y; a.z += v.z; a.w += v.w;
    }

    __shared__ float4 red[16][16];
    red[s][g] = a;
    __syncthreads();

    #pragma unroll
    for (int step = 8; step >= 1; step >>= 1) {
        if (s < step) {
            float4 o = red[s + step][g];
            red[s][g].x += o.x; red[s][g].y += o.y;
            red[s][g].z += o.z; red[s][g].w += o.w;
        }
        __syncthreads();
    }

    if (s == 0) {
        const float sc = 0.05f / 2048.0f;
        float4 r = red[0][g];
        r.x *= sc; r.y *= sc; r.z *= sc; r.w *= sc;
        reinterpret_cast<float4*>(
            out + ((size_t)(b * (K_ + 1) + K_)) * D_)[c4] = r;
    }
}

extern "C" void kernel_launch(void* const* d_in, const int* in_sizes, int n_in,
                              void* d_out, int out_size) {
    const float* seq  = (const float*)d_in[0];   // (16, 4096, 1024) fp32
    const float* attn = (const float*)d_in[1];   // (16, 4096) fp32
    float* out = (float*)d_out;                  // (16, 2049, 1024) fp32
    (void)in_sizes; (void)n_in; (void)out_size;

    sort_rank_kernel<<<B_, 1024>>>(attn);
    fused_kernel    <<<dim3(BLKS_PER_B_, B_), 256>>>(seq, out);
    rem_kernel      <<<dim3(B_, 16), 256>>>(out);
}

// round 8
// speedup vs baseline: 1.1023x; 1.1023x over previous
#include <cuda_runtime.h>

#define B_  16
#define N_  4096
#define D_  1024
#define K_  2048

#define TOK_ 32          // tokens per fused block
#define BLKS_PER_B_ (N_ / TOK_)   // 128

__device__ int   g_rank[B_ * N_];
__device__ float g_partial[B_ * BLKS_PER_B_ * D_];

__device__ __forceinline__ unsigned ord32(float v) {
    unsigned bits = __float_as_uint(v);
    return (bits & 0x80000000u) ? ~bits : (bits | 0x80000000u);
}

// -------------------------------------------------------------------------
// Kernel A: exact descending rank via counting (O(N), no sort).
// grid (B), block 1024. Keys: ord32 (order-preserving u32). Bins: top 12
// bits, reversed so ascending bin == descending key. pref[bin] = # elements
// with strictly larger bin; within-bin rank by scanning the bin's member
// list with the exact tie rule (kj>ki)||(kj==ki && j<i), matching
// jax.lax.top_k (descending, stable). Histogram & scatter offsets use
// 2-bins-per-u32 packed smem atomics (counts < 65536 => no carry).
// Scatter order within a bin is nondeterministic but is only a membership
// list; the rank count over the full segment is order-invariant.
// -------------------------------------------------------------------------
__global__ void __launch_bounds__(1024)
rank_kernel(const float* __restrict__ attn) {
    __shared__ unsigned       skey[N_];          // 16 KB
    __shared__ unsigned       atom[N_ / 2];      //  8 KB packed counters
    __shared__ unsigned short pref[N_ + 1];      //  8 KB
    __shared__ unsigned short sorted[N_];        //  8 KB
    __shared__ int            warp_tot[32];

    const int b = blockIdx.x;
    const int t = threadIdx.x;

    // 1. load keys, zero packed counters
    #pragma unroll
    for (int p = 0; p < 4; p++)
        skey[p * 1024 + t] = ord32(attn[b * N_ + p * 1024 + t]);
    #pragma unroll
    for (int p = 0; p < 2; p++)
        atom[p * 1024 + t] = 0u;
    __syncthreads();

    // 2. histogram (bin = 4095 - top12(key); packed atomics)
    #pragma unroll
    for (int p = 0; p < 4; p++) {
        const unsigned bin = 4095u - (skey[p * 1024 + t] >> 20);
        atomicAdd(&atom[bin >> 1], 1u << ((bin & 1u) * 16));
    }
    __syncthreads();

    // 3. exclusive prefix sum over 4096 bins (thread t owns bins 4t..4t+3)
    const unsigned w0 = atom[2 * t], w1 = atom[2 * t + 1];
    const int c0 = w0 & 0xFFFF, c1 = w0 >> 16;
    const int c2 = w1 & 0xFFFF, c3 = w1 >> 16;
    const int local = c0 + c1 + c2 + c3;
    const int lane = t & 31, wid = t >> 5;

    int scan = local;
    #pragma unroll
    for (int d = 1; d < 32; d <<= 1) {
        const int v = __shfl_up_sync(0xffffffffu, scan, d);
        if (lane >= d) scan += v;
    }
    if (lane == 31) warp_tot[wid] = scan;
    __syncthreads();
    if (wid == 0) {
        const int v = warp_tot[lane];
        int s = v;
        #pragma unroll
        for (int d = 1; d < 32; d <<= 1) {
            const int u = __shfl_up_sync(0xffffffffu, s, d);
            if (lane >= d) s += u;
        }
        warp_tot[lane] = s - v;     // exclusive warp offset
    }
    __syncthreads();
    const int off = warp_tot[wid] + (scan - local);
    pref[4 * t]     = (unsigned short)(off);
    pref[4 * t + 1] = (unsigned short)(off + c0);
    pref[4 * t + 2] = (unsigned short)(off + c0 + c1);
    pref[4 * t + 3] = (unsigned short)(off + c0 + c1 + c2);
    if (t == 1023) pref[N_] = (unsigned short)(off + local);
    // reset packed counters for scatter
    atom[2 * t] = 0u;
    atom[2 * t + 1] = 0u;
    __syncthreads();

    // 4. scatter element ids into bin segments
    #pragma unroll
    for (int p = 0; p < 4; p++) {
        const int i = p * 1024 + t;
        const unsigned bin = 4095u - (skey[i] >> 20);
        const unsigned sh  = (bin & 1u) * 16;
        const unsigned old = atomicAdd(&atom[bin >> 1], 1u << sh);
        const int pos = (int)pref[bin] + (int)((old >> sh) & 0xFFFFu);
        sorted[pos] = (unsigned short)i;
    }
    __syncthreads();

    // 5. exact rank = pref[bin] + count-larger within segment
    #pragma unroll
    for (int p = 0; p < 4; p++) {
        const int i = p * 1024 + t;
        const unsigned ki  = skey[i];
        const unsigned bin = 4095u - (ki >> 20);
        const int s0  = pref[bin];
        const int len = (int)pref[bin + 1] - s0;
        int r = s0;
        for (int q = 0; q < len; q++) {
            const int j = sorted[s0 + q];
            const unsigned kj = skey[j];
            r += (kj > ki) || (kj == ki && j < i);
        }
        g_rank[b * N_ + i] = r;
    }
}

// -------------------------------------------------------------------------
// Kernel B: fused gather + pruned-sum. grid (BLKS_PER_B, B), block 256.
// Streams TOK_ consecutive token rows (sequential 128KB read per block).
// Per-token branch is uniform across the block (no divergence):
//   rank < K : write row to out[b, rank, :]
//   else     : accumulate into per-thread float4 partial
// -------------------------------------------------------------------------
__global__ void __launch_bounds__(256)
fused_kernel(const float* __restrict__ seq, float* __restrict__ out) {
    const int b   = blockIdx.y;
    const int blk = blockIdx.x;
    const int t   = threadIdx.x;
    const int n0  = blk * TOK_;

    const float4* __restrict__ src =
        reinterpret_cast<const float4*>(seq + ((size_t)(b * N_ + n0)) * D_);
    const int* __restrict__ rnk = g_rank + b * N_ + n0;

    float4 acc = make_float4(0.f, 0.f, 0.f, 0.f);

    #pragma unroll 8
    for (int k = 0; k < TOK_; k++) {
        const float4 v = src[k * (D_ / 4) + t];
        const int r = rnk[k];
        if (r < K_) {
            reinterpret_cast<float4*>(
                out + ((size_t)(b * (K_ + 1) + r)) * D_)[t] = v;
        } else {
            acc.x += v.x; acc.y += v.y; acc.z += v.z; acc.w += v.w;
        }
    }

    reinterpret_cast<float4*>(g_partial)
        [((size_t)b * BLKS_PER_B_ + blk) * (D_ / 4) + t] = acc;
}

// -------------------------------------------------------------------------
// Kernel C: reduce partials, write mixup row out[b, K, :].
// grid (B, 16), block 256. rem_cnt = 2048 + 1e-10 == 2048.0f in fp32.
// -------------------------------------------------------------------------
__global__ void __launch_bounds__(256)
rem_kernel(float* __restrict__ out) {
    const int b  = blockIdx.x;
    const int g  = threadIdx.x & 15;
    const int s  = threadIdx.x >> 4;
    const int c4 = blockIdx.y * 16 + g;

    const float4* __restrict__ p =
        reinterpret_cast<const float4*>(g_partial) +
        (size_t)b * BLKS_PER_B_ * (D_ / 4) + c4;

    float4 a = make_float4(0.f, 0.f, 0.f, 0.f);
    #pragma unroll
    for (int m = 0; m < 8; m++) {
        const float4 v = p[(size_t)(s + 16 * m) * (D_ / 4)];
        a.x += v.x; a.y += v.y; a.z += v.z; a.w += v.w;
    }

    __shared__ float4 red[16][16];
    red[s][g] = a;
    __syncthreads();

    #pragma unroll
    for (int step = 8; step >= 1; step >>= 1) {
        if (s < step) {
            float4 o = red[s + step][g];
            red[s][g].x += o.x; red[s][g].y += o.y;
            red[s][g].z += o.z; red[s][g].w += o.w;
        }
        __syncthreads();
    }

    if (s == 0) {
        const float sc = 0.05f / 2048.0f;
        float4 r = red[0][g];
        r.x *= sc; r.y *= sc; r.z *= sc; r.w *= sc;
        reinterpret_cast<float4*>(
            out + ((size_t)(b * (K_ + 1) + K_)) * D_)[c4] = r;
    }
}

extern "C" void kernel_launch(void* const* d_in, const int* in_sizes, int n_in,
                              void* d_out, int out_size) {
    const float* seq  = (const float*)d_in[0];   // (16, 4096, 1024) fp32
    const float* attn = (const float*)d_in[1];   // (16, 4096) fp32
    float* out = (float*)d_out;                  // (16, 2049, 1024) fp32
    (void)in_sizes; (void)n_in; (void)out_size;

    rank_kernel <<<B_, 1024>>>(attn);
    fused_kernel<<<dim3(BLKS_PER_B_, B_), 256>>>(seq, out);
    rem_kernel  <<<dim3(B_, 16), 256>>>(out);
}

// round 10
// speedup vs baseline: 1.1493x; 1.0427x over previous
#include <cuda_runtime.h>

#define B_  16
#define N_  4096
#define D_  1024
#define K_  2048

#define TOK_ 32
#define BLKS_PER_B_ (N_ / TOK_)   // 128
#define NSUM_PER_B_ 16            // total-sum blocks per batch
#define SUMROWS_ 64               // rows per 256-thread group in sum path

__device__ int   g_rank[B_ * N_];
__device__ float g_selpart[B_ * BLKS_PER_B_ * D_];   // selected-row partials
__device__ float g_totpart[B_ * 64 * D_];            // total-sum partials

__device__ __forceinline__ unsigned ord32(float v) {
    unsigned bits = __float_as_uint(v);
    return (bits & 0x80000000u) ? ~bits : (bits | 0x80000000u);
}

// -------------------------------------------------------------------------
// Kernel 1: blocks [0,16)  -> exact descending rank per batch (counting).
//           blocks [16,272)-> total column-sum of ALL rows (no ranks
//                             needed), saturating HBM on the SMs the rank
//                             blocks leave idle. One launch, two roles.
//
// Rank method: bin = top-12-bits of order-preserving key (reversed so
// ascending bin == descending value). pref = exclusive bin prefix.
// Within a bin all keys share their top 12 bits, so the tie-break key is
// packed into u32: (key << 12) | (4095 - idx) — the shift drops the bin
// bits; u32 '>' within a segment == (vj>vi)||(vj==vi && j<i), i.e. exactly
// jax.lax.top_k's order (value desc, index asc). The count over the
// segment is invariant to scatter order. smem: 8KB atom + 8KB pref +
// 16KB seg = 32KB dynamic (+128B static) — under the 48KB default.
// -------------------------------------------------------------------------
__global__ void __launch_bounds__(1024)
k1_rank_totsum(const float* __restrict__ attn, const float* __restrict__ seq) {
    extern __shared__ unsigned char smraw[];
    const int t = threadIdx.x;

    if (blockIdx.x < B_) {
        // ---------------- rank path ----------------
        unsigned*       atom = reinterpret_cast<unsigned*>(smraw);               // 8KB
        unsigned short* pref = reinterpret_cast<unsigned short*>(smraw + 8192);  // 8KB
        unsigned*       seg  = reinterpret_cast<unsigned*>(smraw + 16384);       // 16KB
        __shared__ int warp_tot[32];

        const int b = blockIdx.x;

        unsigned key[4];
        #pragma unroll
        for (int p = 0; p < 4; p++)
            key[p] = ord32(attn[b * N_ + p * 1024 + t]);
        atom[t] = 0u; atom[t + 1024] = 0u;
        __syncthreads();

        #pragma unroll
        for (int p = 0; p < 4; p++) {
            const unsigned bin = 4095u - (key[p] >> 20);
            atomicAdd(&atom[bin >> 1], 1u << ((bin & 1u) * 16));
        }
        __syncthreads();

        // exclusive scan over 4096 bins (thread t owns bins 4t..4t+3)
        const unsigned w0 = atom[2 * t], w1 = atom[2 * t + 1];
        const int c0 = w0 & 0xFFFF, c1 = w0 >> 16;
        const int c2 = w1 & 0xFFFF, c3 = w1 >> 16;
        const int local = c0 + c1 + c2 + c3;
        const int lane = t & 31, wid = t >> 5;

        int scan = local;
        #pragma unroll
        for (int d = 1; d < 32; d <<= 1) {
            const int v = __shfl_up_sync(0xffffffffu, scan, d);
            if (lane >= d) scan += v;
        }
        if (lane == 31) warp_tot[wid] = scan;
        __syncthreads();
        if (wid == 0) {
            const int v = warp_tot[lane];
            int s = v;
            #pragma unroll
            for (int d = 1; d < 32; d <<= 1) {
                const int u = __shfl_up_sync(0xffffffffu, s, d);
                if (lane >= d) s += u;
            }
            warp_tot[lane] = s - v;
        }
        __syncthreads();
        const int off = warp_tot[wid] + (scan - local);
        pref[4 * t]     = (unsigned short)(off);
        pref[4 * t + 1] = (unsigned short)(off + c0);
        pref[4 * t + 2] = (unsigned short)(off + c0 + c1);
        pref[4 * t + 3] = (unsigned short)(off + c0 + c1 + c2);
        atom[2 * t] = 0u; atom[2 * t + 1] = 0u;
        __syncthreads();

        // scatter packed u32 tie-keys into segments
        #pragma unroll
        for (int p = 0; p < 4; p++) {
            const int i = p * 1024 + t;
            const unsigned bin = 4095u - (key[p] >> 20);
            const unsigned sh  = (bin & 1u) * 16;
            const unsigned old = atomicAdd(&atom[bin >> 1], 1u << sh);
            const int pos = (int)pref[bin] + (int)((old >> sh) & 0xFFFFu);
            seg[pos] = (key[p] << 12) | (unsigned)(4095 - i);
        }
        __syncthreads();

        // exact rank: sequential LDS.32 + compare over own segment
        #pragma unroll
        for (int p = 0; p < 4; p++) {
            const int i = p * 1024 + t;
            const unsigned ki  = (key[p] << 12) | (unsigned)(4095 - i);
            const unsigned bin = 4095u - (key[p] >> 20);
            const int s0  = pref[bin];
            const int end = (bin == 4095u) ? N_ : (int)pref[bin + 1];
            int r = s0;
            for (int q = s0; q < end; q++) r += (seg[q] > ki);
            g_rank[b * N_ + i] = r;
        }
    } else {
        // ---------------- total-sum path ----------------
        const int s     = blockIdx.x - B_;        // 0..255
        const int b     = s >> 4;
        const int chunk = s & 15;
        const int g     = t >> 8;                 // 0..3
        const int tt    = t & 255;                // col f4
        const int n0    = chunk * 256 + g * SUMROWS_;

        const float4* __restrict__ src =
            reinterpret_cast<const float4*>(seq + ((size_t)(b * N_ + n0)) * D_);

        float4 acc = make_float4(0.f, 0.f, 0.f, 0.f);
        #pragma unroll 4
        for (int r = 0; r < SUMROWS_; r++) {
            const float4 v = src[(size_t)r * (D_ / 4) + tt];
            acc.x += v.x; acc.y += v.y; acc.z += v.z; acc.w += v.w;
        }
        const int j = chunk * 4 + g;              // 0..63 partial slot
        reinterpret_cast<float4*>(g_totpart)
            [((size_t)(b * 64 + j)) * (D_ / 4) + tt] = acc;
    }
}

// -------------------------------------------------------------------------
// Kernel 2: gather selected rows + selected-sum partials.
// grid (BLKS_PER_B, B), block 256. Reads ONLY selected rows (half of seq).
// Per-token branch is uniform across the block.
// -------------------------------------------------------------------------
__global__ void __launch_bounds__(256)
gather_kernel(const float* __restrict__ seq, float* __restrict__ out) {
    const int b   = blockIdx.y;
    const int blk = blockIdx.x;
    const int t   = threadIdx.x;
    const int n0  = blk * TOK_;

    const float4* __restrict__ src =
        reinterpret_cast<const float4*>(seq + ((size_t)(b * N_ + n0)) * D_);
    const int* __restrict__ rnk = g_rank + b * N_ + n0;

    float4 acc = make_float4(0.f, 0.f, 0.f, 0.f);

    #pragma unroll 8
    for (int k = 0; k < TOK_; k++) {
        const int r = rnk[k];
        if (r < K_) {
            const float4 v = src[k * (D_ / 4) + t];
            reinterpret_cast<float4*>(
                out + ((size_t)(b * (K_ + 1) + r)) * D_)[t] = v;
            acc.x += v.x; acc.y += v.y; acc.z += v.z; acc.w += v.w;
        }
    }

    reinterpret_cast<float4*>(g_selpart)
        [((size_t)b * BLKS_PER_B_ + blk) * (D_ / 4) + t] = acc;
}

// -------------------------------------------------------------------------
// Kernel 3: rem row = 0.05 * (total - selected) / 2048.
// grid (B, 16), block 256. (2048 + 1e-10 == 2048.0f in fp32.)
// -------------------------------------------------------------------------
__global__ void __launch_bounds__(256)
rem_kernel(float* __restrict__ out) {
    const int b  = blockIdx.x;
    const int g  = threadIdx.x & 15;
    const int s  = threadIdx.x >> 4;
    const int c4 = blockIdx.y * 16 + g;

    const float4* __restrict__ ps =
        reinterpret_cast<const float4*>(g_selpart) +
        (size_t)b * BLKS_PER_B_ * (D_ / 4) + c4;
    const float4* __restrict__ pt =
        reinterpret_cast<const float4*>(g_totpart) +
        (size_t)b * 64 * (D_ / 4) + c4;

    float4 a = make_float4(0.f, 0.f, 0.f, 0.f);
    #pragma unroll
    for (int m = 0; m < 4; m++) {   // total partials (64)
        const float4 v = pt[(size_t)(s + 16 * m) * (D_ / 4)];
        a.x += v.x; a.y += v.y; a.z += v.z; a.w += v.w;
    }
    #pragma unroll
    for (int m = 0; m < 8; m++) {   // minus selected partials (128)
        const float4 v = ps[(size_t)(s + 16 * m) * (D_ / 4)];
        a.x -= v.x; a.y -= v.y; a.z -= v.z; a.w -= v.w;
    }

    __shared__ float4 red[16][16];
    red[s][g] = a;
    __syncthreads();

    #pragma unroll
    for (int step = 8; step >= 1; step >>= 1) {
        if (s < step) {
            float4 o = red[s + step][g];
            red[s][g].x += o.x; red[s][g].y += o.y;
            red[s][g].z += o.z; red[s][g].w += o.w;
        }
        __syncthreads();
    }

    if (s == 0) {
        const float sc = 0.05f / 2048.0f;
        float4 r = red[0][g];
        r.x *= sc; r.y *= sc; r.z *= sc; r.w *= sc;
        reinterpret_cast<float4*>(
            out + ((size_t)(b * (K_ + 1) + K_)) * D_)[c4] = r;
    }
}

extern "C" void kernel_launch(void* const* d_in, const int* in_sizes, int n_in,
                              void* d_out, int out_size) {
    const float* seq  = (const float*)d_in[0];   // (16, 4096, 1024) fp32
    const float* attn = (const float*)d_in[1];   // (16, 4096) fp32
    float* out = (float*)d_out;                  // (16, 2049, 1024) fp32
    (void)in_sizes; (void)n_in; (void)out_size;

    const int smem = 8192 + 8192 + 16384;        // 32KB dynamic (rank blocks)
    k1_rank_totsum<<<B_ + B_ * NSUM_PER_B_, 1024, smem>>>(attn, seq);
    gather_kernel <<<dim3(BLKS_PER_B_, B_), 256>>>(seq, out);
    rem_kernel    <<<dim3(B_, 16), 256>>>(out);
}

// round 11
// speedup vs baseline: 1.3304x; 1.1576x over previous
#include <cuda_runtime.h>

#define B_  16
#define N_  4096
#define D_  1024
#define K_  2048

#define TOK_ 32
#define BLKS_PER_B_ (N_ / TOK_)   // 128
#define PF_BLKS_ 256              // prefetch blocks (64 rows each)

__device__ unsigned       g_seg[B_ * N_];          // packed tie-keys by segment
__device__ unsigned short g_pref[B_ * (N_ + 1)];   // exclusive bin prefix + sentinel
__device__ float g_part[B_ * BLKS_PER_B_ * D_];    // pruned partials
__device__ float g_sink[32768];                    // prefetch sink (never read)

__device__ __forceinline__ unsigned ord32(float v) {
    unsigned bits = __float_as_uint(v);
    return (bits & 0x80000000u) ? ~bits : (bits | 0x80000000u);
}

// -------------------------------------------------------------------------
// K1: blocks [0,16)    -> per-batch bin structure: histogram of top-12-bit
//                         (reversed) key bins, exclusive scan, scatter of
//                         packed u32 tie-keys (key<<12)|(4095-idx) into
//                         gmem segments. No count phase here.
//     blocks [16,272)  -> prefetch rows [0,1024) of each batch into L2
//                         (the fused kernel's first waves read them).
// -------------------------------------------------------------------------
__global__ void __launch_bounds__(1024)
k1_bins_prefetch(const float* __restrict__ attn, const float* __restrict__ seq) {
    const int t = threadIdx.x;

    if (blockIdx.x < B_) {
        __shared__ unsigned       atom[N_ / 2];   // 8KB packed counters
        __shared__ unsigned short pref[N_];       // 8KB
        __shared__ int warp_tot[32];

        const int b = blockIdx.x;

        unsigned key[4];
        #pragma unroll
        for (int p = 0; p < 4; p++)
            key[p] = ord32(attn[b * N_ + p * 1024 + t]);
        atom[t] = 0u; atom[t + 1024] = 0u;
        __syncthreads();

        #pragma unroll
        for (int p = 0; p < 4; p++) {
            const unsigned bin = 4095u - (key[p] >> 20);
            atomicAdd(&atom[bin >> 1], 1u << ((bin & 1u) * 16));
        }
        __syncthreads();

        // exclusive scan over 4096 bins (thread t owns bins 4t..4t+3)
        const unsigned w0 = atom[2 * t], w1 = atom[2 * t + 1];
        const int c0 = w0 & 0xFFFF, c1 = w0 >> 16;
        const int c2 = w1 & 0xFFFF, c3 = w1 >> 16;
        const int local = c0 + c1 + c2 + c3;
        const int lane = t & 31, wid = t >> 5;

        int scan = local;
        #pragma unroll
        for (int d = 1; d < 32; d <<= 1) {
            const int v = __shfl_up_sync(0xffffffffu, scan, d);
            if (lane >= d) scan += v;
        }
        if (lane == 31) warp_tot[wid] = scan;
        __syncthreads();
        if (wid == 0) {
            const int v = warp_tot[lane];
            int s = v;
            #pragma unroll
            for (int d = 1; d < 32; d <<= 1) {
                const int u = __shfl_up_sync(0xffffffffu, s, d);
                if (lane >= d) s += u;
            }
            warp_tot[lane] = s - v;
        }
        __syncthreads();
        const int off = warp_tot[wid] + (scan - local);
        const unsigned short p0 = (unsigned short)(off);
        const unsigned short p1 = (unsigned short)(off + c0);
        const unsigned short p2 = (unsigned short)(off + c0 + c1);
        const unsigned short p3 = (unsigned short)(off + c0 + c1 + c2);
        pref[4 * t] = p0; pref[4 * t + 1] = p1;
        pref[4 * t + 2] = p2; pref[4 * t + 3] = p3;
        unsigned short* __restrict__ gp = g_pref + b * (N_ + 1);
        gp[4 * t] = p0; gp[4 * t + 1] = p1;
        gp[4 * t + 2] = p2; gp[4 * t + 3] = p3;
        if (t == 0) gp[N_] = (unsigned short)N_;   // sentinel
        atom[2 * t] = 0u; atom[2 * t + 1] = 0u;
        __syncthreads();

        // scatter packed tie-keys straight to gmem segments
        #pragma unroll
        for (int p = 0; p < 4; p++) {
            const int i = p * 1024 + t;
            const unsigned bin = 4095u - (key[p] >> 20);
            const unsigned sh  = (bin & 1u) * 16;
            const unsigned old = atomicAdd(&atom[bin >> 1], 1u << sh);
            const int pos = (int)pref[bin] + (int)((old >> sh) & 0xFFFFu);
            g_seg[b * N_ + pos] = (key[p] << 12) | (unsigned)(4095 - i);
        }
    } else {
        // ---------- prefetch rows [0,1024) per batch into L2 ----------
        const int s  = blockIdx.x - B_;      // 0..255
        const int b  = s >> 4;
        const int c  = s & 15;
        const int g  = t >> 8;               // 0..3
        const int tt = t & 255;
        const int n0 = c * 64 + g * 16;      // 64 rows/block, 16/group

        const float4* __restrict__ src =
            reinterpret_cast<const float4*>(seq + ((size_t)(b * N_ + n0)) * D_);

        float4 a = make_float4(0.f, 0.f, 0.f, 0.f);
        #pragma unroll 4
        for (int r = 0; r < 16; r++) {
            const float4 v = src[(size_t)r * (D_ / 4) + tt];
            a.x += v.x; a.y += v.y; a.z += v.z; a.w += v.w;
        }
        // sink (never read; racy content is fine, d_out never depends on it)
        reinterpret_cast<float4*>(g_sink)[(((s * 4 + g) & 31) * 256) + tt] = a;
    }
}

// -------------------------------------------------------------------------
// K2: fused rank-count + gather + pruned-sum. grid (BLKS_PER_B, B), blk 256.
// Warp 0 first computes the block's 32 ranks from the L2-resident bin
// structure: rank = pref[bin] + #(seg[q] > packed_key) — order-invariant,
// exactly jax.lax.top_k's order (value desc, index asc). Then the block
// streams its 32 rows (128KB sequential read): selected rows are written
// to out[b, rank, :], pruned rows accumulate into a per-block partial.
// -------------------------------------------------------------------------
__global__ void __launch_bounds__(256)
fused_kernel(const float* __restrict__ seq, const float* __restrict__ attn,
             float* __restrict__ out) {
    __shared__ int srank[TOK_];
    const int b   = blockIdx.y;
    const int blk = blockIdx.x;
    const int t   = threadIdx.x;
    const int n0  = blk * TOK_;

    if (t < TOK_) {
        const int i = n0 + t;
        const unsigned key = ord32(attn[b * N_ + i]);
        const unsigned ki  = (key << 12) | (unsigned)(4095 - i);
        const unsigned bin = 4095u - (key >> 20);
        const unsigned short* __restrict__ gp = g_pref + b * (N_ + 1);
        const int s0  = gp[bin];
        const int end = gp[bin + 1];
        const unsigned* __restrict__ sg = g_seg + b * N_;
        int r = s0;
        for (int q = s0; q < end; q++) r += (sg[q] > ki);
        srank[t] = r;
    }
    __syncthreads();

    const float4* __restrict__ src =
        reinterpret_cast<const float4*>(seq + ((size_t)(b * N_ + n0)) * D_);

    float4 acc = make_float4(0.f, 0.f, 0.f, 0.f);

    #pragma unroll 8
    for (int k = 0; k < TOK_; k++) {
        const float4 v = src[k * (D_ / 4) + t];
        const int r = srank[k];
        if (r < K_) {
            reinterpret_cast<float4*>(
                out + ((size_t)(b * (K_ + 1) + r)) * D_)[t] = v;
        } else {
            acc.x += v.x; acc.y += v.y; acc.z += v.z; acc.w += v.w;
        }
    }

    reinterpret_cast<float4*>(g_part)
        [((size_t)b * BLKS_PER_B_ + blk) * (D_ / 4) + t] = acc;
}

// -------------------------------------------------------------------------
// K3: reduce pruned partials, write mixup row out[b, K, :].
// grid (B, 16), block 256. rem_cnt = 2048 + 1e-10 == 2048.0f in fp32.
// -------------------------------------------------------------------------
__global__ void __launch_bounds__(256)
rem_kernel(float* __restrict__ out) {
    const int b  = blockIdx.x;
    const int g  = threadIdx.x & 15;
    const int s  = threadIdx.x >> 4;
    const int c4 = blockIdx.y * 16 + g;

    const float4* __restrict__ p =
        reinterpret_cast<const float4*>(g_part) +
        (size_t)b * BLKS_PER_B_ * (D_ / 4) + c4;

    float4 a = make_float4(0.f, 0.f, 0.f, 0.f);
    #pragma unroll
    for (int m = 0; m < 8; m++) {
        const float4 v = p[(size_t)(s + 16 * m) * (D_ / 4)];
        a.x += v.x; a.y += v.y; a.z += v.z; a.w += v.w;
    }

    __shared__ float4 red[16][16];
    red[s][g] = a;
    __syncthreads();

    #pragma unroll
    for (int step = 8; step >= 1; step >>= 1) {
        if (s < step) {
            float4 o = red[s + step][g];
            red[s][g].x += o.x; red[s][g].y += o.y;
            red[s][g].z += o.z; red[s][g].w += o.w;
        }
        __syncthreads();
    }

    if (s == 0) {
        const float sc = 0.05f / 2048.0f;
        float4 r = red[0][g];
        r.x *= sc; r.y *= sc; r.z *= sc; r.w *= sc;
        reinterpret_cast<float4*>(
            out + ((size_t)(b * (K_ + 1) + K_)) * D_)[c4] = r;
    }
}

extern "C" void kernel_launch(void* const* d_in, const int* in_sizes, int n_in,
                              void* d_out, int out_size) {
    const float* seq  = (const float*)d_in[0];   // (16, 4096, 1024) fp32
    const float* attn = (const float*)d_in[1];   // (16, 4096) fp32
    float* out = (float*)d_out;                  // (16, 2049, 1024) fp32
    (void)in_sizes; (void)n_in; (void)out_size;

    k1_bins_prefetch<<<B_ + PF_BLKS_, 1024>>>(attn, seq);
    fused_kernel    <<<dim3(BLKS_PER_B_, B_), 256>>>(seq, attn, out);
    rem_kernel      <<<dim3(B_, 16), 256>>>(out);
}